// round 2
// baseline (speedup 1.0000x reference)
#include <cuda_runtime.h>
#include <cuda_bf16.h>
#include <cstdint>

#define NPTS   2048
#define NBATCH 8
#define NSAMP  64
#define R2     0.36f

// 8 MB feature scratch: f[b][m][c], c = 0..127, fp32
__device__ float g_feat[NBATCH * NPTS * 128];

// ---------------------------------------------------------------------------
// Kernel 1: per-point features f[b,m,:] = relu(W2*relu(W1*x+b1)+b2)
// Warp layout: warp = 32 consecutive points (lanes) x one quarter (32 c's).
// All lanes read the SAME W2 element at a time -> smem broadcast, no conflicts.
// Output staged through smem in 8-c chunks so global stores are sector-dense.
// ---------------------------------------------------------------------------
__global__ __launch_bounds__(256) void feat_kernel(
    const float* __restrict__ x, const float* __restrict__ W1,
    const float* __restrict__ b1, const float* __restrict__ W2,
    const float* __restrict__ b2)
{
    __shared__ float  sW1[64 * 3];
    __shared__ float  sb1[64];
    __shared__ float  sb2[128];
    __shared__ float4 sW2[128 * 16];        // [c][o/4], 32 KB
    __shared__ float  stile[8][32 * 9];     // per-warp staging [p][c_chunk], pad 9

    const int tid = threadIdx.x;
    for (int i = tid; i < 192; i += blockDim.x) sW1[i] = W1[i];
    for (int i = tid; i < 64;  i += blockDim.x) sb1[i] = b1[i];
    for (int i = tid; i < 128; i += blockDim.x) sb2[i] = b2[i];
    for (int i = tid; i < 128 * 16; i += blockDim.x)
        sW2[i] = reinterpret_cast<const float4*>(W2)[i];
    __syncthreads();

    const int lane    = tid & 31;
    const int wlocal  = tid >> 5;
    const int gwarp   = blockIdx.x * 8 + wlocal;      // 0..2047
    const int quarter = gwarp & 3;                    // which 32 c's
    const int pbase   = (gwarp >> 2) * 32;            // 32 points per warp
    const int p       = pbase + lane;

    const float x0 = x[p * 3 + 0];
    const float x1 = x[p * 3 + 1];
    const float x2 = x[p * 3 + 2];

    // hidden layer (64), kept in registers
    float h1[64];
#pragma unroll
    for (int o = 0; o < 64; o++) {
        float v = sb1[o];
        v = fmaf(sW1[o * 3 + 0], x0, v);
        v = fmaf(sW1[o * 3 + 1], x1, v);
        v = fmaf(sW1[o * 3 + 2], x2, v);
        h1[o] = fmaxf(v, 0.0f);
    }

    const int cbase = quarter * 32;
    float* tile = &stile[wlocal][0];

    for (int chunk = 0; chunk < 4; chunk++) {
#pragma unroll
        for (int j = 0; j < 8; j++) {
            const int c = cbase + chunk * 8 + j;
            float acc = sb2[c];
#pragma unroll
            for (int o4 = 0; o4 < 16; o4++) {
                float4 w = sW2[c * 16 + o4];   // broadcast across warp
                acc = fmaf(w.x, h1[4 * o4 + 0], acc);
                acc = fmaf(w.y, h1[4 * o4 + 1], acc);
                acc = fmaf(w.z, h1[4 * o4 + 2], acc);
                acc = fmaf(w.w, h1[4 * o4 + 3], acc);
            }
            tile[lane * 9 + j] = fmaxf(acc, 0.0f);
        }
        __syncwarp();
        // write 32 points x 8 c's, sector-dense: lane -> (point_row, c)
        const int jr = lane & 7;       // c within chunk
        const int pr = lane >> 3;      // point row group
#pragma unroll
        for (int r = 0; r < 8; r++) {
            const int prow = r * 4 + pr;
            g_feat[(size_t)(pbase + prow) * 128 + cbase + chunk * 8 + jr] =
                tile[prow * 9 + jr];
        }
        __syncwarp();
    }
}

// ---------------------------------------------------------------------------
// Kernel 2: fused ball-query + feature max-pool.
// One warp per query point n. Scan m = 0..2047 in ascending order, accept
// while dist <= R^2 and count < 64 (early break at 64). For each accepted m,
// the warp gathers f[b,m,0:128] (512 B coalesced, L2-resident) and fmax's
// into 4 registers/lane. Output staged through smem for coalesced stores.
// ---------------------------------------------------------------------------
__global__ __launch_bounds__(1024) void group_kernel(
    const float* __restrict__ x, float* __restrict__ out)
{
    __shared__ float smem_buf[NPTS * 4];   // 32 KB: sx (float4) then reused as sout
    float4* sx = reinterpret_cast<float4*>(smem_buf);

    const int b   = blockIdx.y;
    const int n0  = blockIdx.x * 32;
    const int tid = threadIdx.x;
    const float* xb = x + (size_t)b * NPTS * 3;

    for (int p = tid; p < NPTS; p += 1024) {
        const float px = xb[p * 3 + 0];
        const float py = xb[p * 3 + 1];
        const float pz = xb[p * 3 + 2];
        const float sq = px * px + py * py + pz * pz;
        sx[p] = make_float4(px, py, pz, sq);
    }
    __syncthreads();

    const int w    = tid >> 5;
    const int lane = tid & 31;
    const int n    = n0 + w;

    const float4 q = sx[n];
    float a0 = 0.0f, a1 = 0.0f, a2 = 0.0f, a3 = 0.0f;  // relu outputs >= 0
    int count = 0;

    const float4* fb =
        reinterpret_cast<const float4*>(g_feat + (size_t)b * NPTS * 128);

    for (int base = 0; base < NPTS; base += 32) {
        const float4 pm = sx[base + lane];
        // same algebraic form as reference: sq_n + sq_m - 2*dot
        const float dist = q.w + pm.w -
            2.0f * (q.x * pm.x + q.y * pm.y + q.z * pm.z);
        unsigned mask = __ballot_sync(0xffffffffu, !(dist > R2));
        const int cnt  = __popc(mask);
        const int take = min(cnt, NSAMP - count);
        for (int i = 0; i < take; i++) {
            const int j = __ffs(mask) - 1;
            mask &= mask - 1;
            const float4 v = fb[(base + j) * 32 + lane];  // 512 B coalesced
            a0 = fmaxf(a0, v.x);
            a1 = fmaxf(a1, v.y);
            a2 = fmaxf(a2, v.z);
            a3 = fmaxf(a3, v.w);
        }
        count += take;
        if (count >= NSAMP) break;
    }

    // stage result: sout[q][c], row stride 129 to avoid read conflicts
    __syncthreads();                 // everyone done reading sx; reuse buffer
    float* sout = smem_buf;
    float* so = sout + w * 129 + lane * 4;
    so[0] = a0; so[1] = a1; so[2] = a2; so[3] = a3;
    __syncthreads();

    // write out[b, c, n0 + qq]: 32 consecutive n per store -> 128 B coalesced
    float* ob = out + (size_t)b * 128 * NPTS + n0;
    const int qq = tid & 31;
    const int c0 = tid >> 5;
#pragma unroll
    for (int pass = 0; pass < 4; pass++) {
        const int c = pass * 32 + c0;
        ob[(size_t)c * NPTS + qq] = sout[qq * 129 + c];
    }
}

extern "C" void kernel_launch(void* const* d_in, const int* in_sizes, int n_in,
                              void* d_out, int out_size)
{
    const float* x  = (const float*)d_in[0];   // (8, 2048, 3)
    const float* W1 = (const float*)d_in[1];   // (64, 3)
    const float* b1 = (const float*)d_in[2];   // (64,)
    const float* W2 = (const float*)d_in[3];   // (128, 64)
    const float* b2 = (const float*)d_in[4];   // (128,)
    float* out = (float*)d_out;                // (8, 128, 2048)

    feat_kernel<<<256, 256>>>(x, W1, b1, W2, b2);
    group_kernel<<<dim3(64, 8), 1024>>>(x, out);
}